// round 2
// baseline (speedup 1.0000x reference)
#include <cuda_runtime.h>
#include <math.h>

// Problem constants
#define BB   4
#define CIN  32
#define CH   64
#define HH   24
#define WW   24
#define HWN  576          // 24*24
#define TT   5
#define DK   32
#define DV   32
#define NHN  4
#define GG   4
#define HEADS 64          // B*G*NH
#define TKEYS 2880        // T*HW
#define KC    3           // key chunks
#define KPC   960         // keys per chunk
#define QPB   288         // queries per attention block
#define ATTN_THREADS 144  // 2 queries per thread

// ---------------- scratch (device globals; no allocation allowed) -------------
__device__ float  g_xg[BB*GG*CH*HWN];        // conv on inputs, 4 gates x 64 ch
__device__ float  g_co[BB*GG*(CH-DV)*HWN];   // conv on rep, 4 gates x 32 ch
__device__ float4 g_q[HEADS*HWN*2];          // Q [head][q][8] (scaled)
__device__ float4 g_K[HEADS*TKEYS*2];        // K [head][j][8]
__device__ float4 g_V[HEADS*TKEYS*2];        // V [head][j][8]
__device__ float  g_L[KC*HEADS*HWN];         // partial exp-sums
__device__ float4 g_A[KC*HEADS*HWN*2];       // partial weighted V sums
__device__ float  g_attnp[BB*GG*DV*HWN];     // projected attention

// ---------------- conv: 4 gates per thread, 2 pixels per thread --------------
// WHICH = 0 -> write g_xg, WHICH = 1 -> write g_co (device globals referenced
// directly; no device-symbol pointers cross the host boundary).
template<int IC, int OC, int WHICH>
__global__ __launch_bounds__(288)
void conv4g_kernel(const float* __restrict__ in,   // [B][IC][24][24]
                   const float* __restrict__ w,    // [G][OC][IC][3][3]
                   const float* __restrict__ bias) // [G][OC]
{
    const int oc = blockIdx.x;
    const int b  = blockIdx.y;
    const int tid = threadIdx.x;

    __shared__ float ws[GG*IC*9];
    for (int i = tid; i < GG*IC*9; i += 288) {
        int g = i / (IC*9);
        int r = i - g*(IC*9);
        ws[i] = w[(g*OC + oc)*IC*9 + r];
    }
    __syncthreads();

    const int p0 = tid, p1 = tid + 288;
    const int y0 = p0 / WW, x0 = p0 % WW;
    const int y1 = p1 / WW, x1 = p1 % WW;

    float acc0[GG], acc1[GG];
    #pragma unroll
    for (int g = 0; g < GG; g++) {
        float bv = __ldg(bias + g*OC + oc);
        acc0[g] = bv; acc1[g] = bv;
    }

    for (int ic = 0; ic < IC; ic++) {
        const float* ip = in + (b*IC + ic)*HWN;
        float v0[9], v1[9];
        #pragma unroll
        for (int ky = 0; ky < 3; ky++) {
            #pragma unroll
            for (int kx = 0; kx < 3; kx++) {
                int iy = y0 + ky - 1, ix = x0 + kx - 1;
                v0[ky*3+kx] = (iy >= 0 && iy < HH && ix >= 0 && ix < WW)
                              ? __ldg(ip + iy*WW + ix) : 0.f;
                int jy = y1 + ky - 1, jx = x1 + kx - 1;
                v1[ky*3+kx] = (jy >= 0 && jy < HH && jx >= 0 && jx < WW)
                              ? __ldg(ip + jy*WW + jx) : 0.f;
            }
        }
        #pragma unroll
        for (int g = 0; g < GG; g++) {
            const float* wp = &ws[(g*IC + ic)*9];
            #pragma unroll
            for (int kk = 0; kk < 9; kk++) {
                float wv = wp[kk];
                acc0[g] = fmaf(v0[kk], wv, acc0[g]);
                acc1[g] = fmaf(v1[kk], wv, acc1[g]);
            }
        }
    }
    float* out = (WHICH == 0) ? g_xg : g_co;
    #pragma unroll
    for (int g = 0; g < GG; g++) {
        out[((b*GG + g)*OC + oc)*HWN + p0] = acc0[g];
        out[((b*GG + g)*OC + oc)*HWN + p1] = acc1[g];
    }
}

// ---------------- Q projection: Q[head][q][8] = scale*(rep . q_w + b) --------
__global__ __launch_bounds__(144)
void q_kernel(const float* __restrict__ rep,  // [B][CH][HW]
              const float* __restrict__ qw,   // [G][DK][CH]
              const float* __restrict__ qb)   // [G][DK]
{
    const int b = blockIdx.x, g = blockIdx.y, hwc = blockIdx.z;
    const int tid = threadIdx.x;
    const int hw = hwc*144 + tid;

    __shared__ float ws[DK*CH];
    for (int i = tid; i < DK*CH; i += 144) ws[i] = qw[g*DK*CH + i];
    __syncthreads();

    float acc[DK];
    #pragma unroll
    for (int d = 0; d < DK; d++) acc[d] = 0.f;

    for (int c = 0; c < CH; c++) {
        float r = __ldg(rep + (b*CH + c)*HWN + hw);
        #pragma unroll
        for (int d = 0; d < DK; d++) acc[d] = fmaf(r, ws[d*CH + c], acc[d]);
    }

    const float scale = 0.35355339059327373f; // 8^-0.5
    float* qf = (float*)g_q;
    #pragma unroll
    for (int d = 0; d < DK; d++) {
        int n = d >> 3, dd = d & 7;
        int head = (b*GG + g)*NHN + n;
        qf[(head*HWN + hw)*8 + dd] = (acc[d] + __ldg(qb + g*DK + d)) * scale;
    }
}

// ---------------- KV projection (split halves to keep regs low) --------------
// HALF = 0 -> K rows [0,32), HALF = 1 -> V rows [32,64)
template<int HALF>
__global__ __launch_bounds__(144)
void kv_half_kernel(const float* __restrict__ hist, // [B][T][CH][HW]
                    const float* __restrict__ kvw,  // [G][DK+DV][CH]
                    const float* __restrict__ kvb)  // [G][DK+DV]
{
    // blockIdx.x = t*4 + hwchunk, blockIdx.y = b*G + g
    const int t   = blockIdx.x >> 2;
    const int hwc = blockIdx.x & 3;
    const int b   = blockIdx.y >> 2;
    const int g   = blockIdx.y & 3;
    const int tid = threadIdx.x;
    const int hw  = hwc*144 + tid;

    __shared__ float ws[DK*CH];   // this half's 32 rows
    for (int i = tid; i < DK*CH; i += 144)
        ws[i] = kvw[(g*(DK+DV) + HALF*DK)*CH + i];
    __syncthreads();

    float acc[DK];
    #pragma unroll
    for (int e = 0; e < DK; e++) acc[e] = 0.f;

    for (int c = 0; c < CH; c++) {
        float h = __ldg(hist + ((b*TT + t)*CH + c)*HWN + hw);
        #pragma unroll
        for (int e = 0; e < DK; e++) acc[e] = fmaf(h, ws[e*CH + c], acc[e]);
    }

    float* dst = (HALF == 0) ? (float*)g_K : (float*)g_V;
    const int j = t*HWN + hw;
    #pragma unroll
    for (int e = 0; e < DK; e++) {
        int n = e >> 3, d = e & 7;
        int head = (b*GG + g)*NHN + n;
        dst[(head*TKEYS + j)*8 + d] = acc[e] + __ldg(kvb + g*(DK+DV) + HALF*DK + e);
    }
}

// ---------------- attention: exp without max (logits are tiny), linear partials
__global__ __launch_bounds__(ATTN_THREADS)
void attn_kernel()
{
    const int head = blockIdx.x;       // 0..63
    const int qcb  = blockIdx.y;       // 0..1  (q chunk of 288)
    const int kc   = blockIdx.z;       // 0..2  (key chunk of 960)
    const int tid  = threadIdx.x;

    const int q0 = qcb*QPB + tid;
    const int q1 = q0 + ATTN_THREADS;

    const float4* Qp = g_q + head*HWN*2;
    float4 qa0 = __ldg(Qp + q0*2), qb0 = __ldg(Qp + q0*2 + 1);
    float4 qa1 = __ldg(Qp + q1*2), qb1 = __ldg(Qp + q1*2 + 1);

    const float4* Kp = g_K + (head*TKEYS + kc*KPC)*2;
    const float4* Vp = g_V + (head*TKEYS + kc*KPC)*2;

    float l0 = 0.f, l1 = 0.f;
    float acc0[8], acc1[8];
    #pragma unroll
    for (int d = 0; d < 8; d++) { acc0[d] = 0.f; acc1[d] = 0.f; }

    #pragma unroll 4
    for (int j = 0; j < KPC; j++) {
        float4 ka = __ldg(Kp + j*2);
        float4 kb = __ldg(Kp + j*2 + 1);
        float s0 = qa0.x*ka.x + qa0.y*ka.y + qa0.z*ka.z + qa0.w*ka.w
                 + qb0.x*kb.x + qb0.y*kb.y + qb0.z*kb.z + qb0.w*kb.w;
        float s1 = qa1.x*ka.x + qa1.y*ka.y + qa1.z*ka.z + qa1.w*ka.w
                 + qb1.x*kb.x + qb1.y*kb.y + qb1.z*kb.z + qb1.w*kb.w;
        float p0 = __expf(s0);
        float p1 = __expf(s1);
        l0 += p0; l1 += p1;
        float4 va = __ldg(Vp + j*2);
        float4 vb = __ldg(Vp + j*2 + 1);
        acc0[0] = fmaf(p0, va.x, acc0[0]); acc0[1] = fmaf(p0, va.y, acc0[1]);
        acc0[2] = fmaf(p0, va.z, acc0[2]); acc0[3] = fmaf(p0, va.w, acc0[3]);
        acc0[4] = fmaf(p0, vb.x, acc0[4]); acc0[5] = fmaf(p0, vb.y, acc0[5]);
        acc0[6] = fmaf(p0, vb.z, acc0[6]); acc0[7] = fmaf(p0, vb.w, acc0[7]);
        acc1[0] = fmaf(p1, va.x, acc1[0]); acc1[1] = fmaf(p1, va.y, acc1[1]);
        acc1[2] = fmaf(p1, va.z, acc1[2]); acc1[3] = fmaf(p1, va.w, acc1[3]);
        acc1[4] = fmaf(p1, vb.x, acc1[4]); acc1[5] = fmaf(p1, vb.y, acc1[5]);
        acc1[6] = fmaf(p1, vb.z, acc1[6]); acc1[7] = fmaf(p1, vb.w, acc1[7]);
    }

    const int base = (kc*HEADS + head)*HWN;
    g_L[base + q0] = l0;
    g_L[base + q1] = l1;
    g_A[(base + q0)*2    ] = make_float4(acc0[0], acc0[1], acc0[2], acc0[3]);
    g_A[(base + q0)*2 + 1] = make_float4(acc0[4], acc0[5], acc0[6], acc0[7]);
    g_A[(base + q1)*2    ] = make_float4(acc1[0], acc1[1], acc1[2], acc1[3]);
    g_A[(base + q1)*2 + 1] = make_float4(acc1[4], acc1[5], acc1[6], acc1[7]);
}

// ---------------- combine partials + output projection ----------------------
__global__ __launch_bounds__(144)
void proj_kernel(const float* __restrict__ pw,  // [G][DV][DV]
                 const float* __restrict__ pb)  // [G][DV]
{
    const int b = blockIdx.x, g = blockIdx.y, hwc = blockIdx.z;
    const int tid = threadIdx.x;
    const int hw = hwc*144 + tid;

    __shared__ float ws[DV*DV];
    for (int i = tid; i < DV*DV; i += 144) ws[i] = pw[g*DV*DV + i];
    __syncthreads();

    float av[DV];
    #pragma unroll
    for (int n = 0; n < NHN; n++) {
        int head = (b*GG + g)*NHN + n;
        int qi = head*HWN + hw;
        float l = g_L[qi] + g_L[HEADS*HWN + qi] + g_L[2*HEADS*HWN + qi];
        float inv = 1.f / l;
        float4 a0 = g_A[qi*2],                    a1 = g_A[qi*2 + 1];
        float4 b0 = g_A[(HEADS*HWN + qi)*2],      b1 = g_A[(HEADS*HWN + qi)*2 + 1];
        float4 c0 = g_A[(2*HEADS*HWN + qi)*2],    c1 = g_A[(2*HEADS*HWN + qi)*2 + 1];
        av[n*8 + 0] = (a0.x + b0.x + c0.x) * inv;
        av[n*8 + 1] = (a0.y + b0.y + c0.y) * inv;
        av[n*8 + 2] = (a0.z + b0.z + c0.z) * inv;
        av[n*8 + 3] = (a0.w + b0.w + c0.w) * inv;
        av[n*8 + 4] = (a1.x + b1.x + c1.x) * inv;
        av[n*8 + 5] = (a1.y + b1.y + c1.y) * inv;
        av[n*8 + 6] = (a1.z + b1.z + c1.z) * inv;
        av[n*8 + 7] = (a1.w + b1.w + c1.w) * inv;
    }

    #pragma unroll 4
    for (int dout = 0; dout < DV; dout++) {
        float o = __ldg(pb + g*DV + dout);
        #pragma unroll
        for (int di = 0; di < DV; di++) o = fmaf(av[di], ws[dout*DV + di], o);
        g_attnp[((b*GG + g)*DV + dout)*HWN + hw] = o;
    }
}

// ---------------- LSTM gates ------------------------------------------------
__device__ __forceinline__ float sigmf(float x) { return 1.f / (1.f + __expf(-x)); }

__global__ __launch_bounds__(576)
void gates_kernel(const float* __restrict__ c_in,
                  const float* __restrict__ Wci,
                  const float* __restrict__ Wcf,
                  const float* __restrict__ Wco,
                  float* __restrict__ out)
{
    const int b  = blockIdx.x >> 6;
    const int ch = blockIdx.x & 63;
    const int hw = threadIdx.x;

    float pre[GG];
    #pragma unroll
    for (int g = 0; g < GG; g++) {
        float x = g_xg[((b*GG + g)*CH + ch)*HWN + hw];
        float y = (ch < 32) ? g_co[((b*GG + g)*(CH-DV) + ch)*HWN + hw]
                            : g_attnp[((b*GG + g)*DV + (ch - 32))*HWN + hw];
        pre[g] = x + y;
    }

    float c  = __ldg(c_in + (b*CH + ch)*HWN + hw);
    float ci = __ldg(Wci + ch*HWN + hw);
    float cf = __ldg(Wcf + ch*HWN + hw);
    float co = __ldg(Wco + ch*HWN + hw);

    float i_t = sigmf(pre[0] + c*ci);
    float f_t = sigmf(pre[1] + c*cf + 1.0f);
    float c_t = f_t*c + i_t*tanhf(pre[2]);
    float o_t = sigmf(pre[3] + c_t*co);
    float h_t = o_t*tanhf(c_t);

    const int idx = (b*CH + ch)*HWN + hw;
    out[idx] = h_t;
    out[BB*CH*HWN + idx] = c_t;
}

// ---------------- launcher ---------------------------------------------------
extern "C" void kernel_launch(void* const* d_in, const int* in_sizes, int n_in,
                              void* d_out, int out_size)
{
    const float* inputs  = (const float*)d_in[0];
    const float* rep     = (const float*)d_in[1];
    const float* c_in    = (const float*)d_in[2];
    const float* history = (const float*)d_in[3];
    const float* Wx_w    = (const float*)d_in[4];
    const float* Wx_b    = (const float*)d_in[5];
    const float* conv_w  = (const float*)d_in[6];
    const float* conv_b  = (const float*)d_in[7];
    const float* q_w     = (const float*)d_in[8];
    const float* q_b     = (const float*)d_in[9];
    const float* kv_w    = (const float*)d_in[10];
    const float* kv_b    = (const float*)d_in[11];
    const float* proj_w  = (const float*)d_in[12];
    const float* proj_b  = (const float*)d_in[13];
    const float* Wci     = (const float*)d_in[14];
    const float* Wcf     = (const float*)d_in[15];
    const float* Wco     = (const float*)d_in[16];
    float* out = (float*)d_out;
    (void)in_sizes; (void)n_in; (void)out_size;

    // conv on inputs: oc in [0,64), 4 gates per thread -> g_xg
    conv4g_kernel<CIN, CH, 0><<<dim3(CH, BB), 288>>>(inputs, Wx_w, Wx_b);
    // conv on rep: oc in [0,32) -> g_co
    conv4g_kernel<CH, CH-DV, 1><<<dim3(CH-DV, BB), 288>>>(rep, conv_w, conv_b);
    // Q projection
    q_kernel<<<dim3(BB, GG, 4), 144>>>(rep, q_w, q_b);
    // KV projection, two halves (K then V) to keep register pressure low
    kv_half_kernel<0><<<dim3(TT*4, BB*GG), 144>>>(history, kv_w, kv_b);
    kv_half_kernel<1><<<dim3(TT*4, BB*GG), 144>>>(history, kv_w, kv_b);
    // attention (partials over 3 key chunks)
    attn_kernel<<<dim3(HEADS, 2, KC), ATTN_THREADS>>>();
    // combine + projection
    proj_kernel<<<dim3(BB, GG, 4), 144>>>(proj_w, proj_b);
    // LSTM gates -> h_t, c_t
    gates_kernel<<<BB*CH, HWN>>>(c_in, Wci, Wcf, Wco, out);
}

// round 3
// speedup vs baseline: 1.5420x; 1.5420x over previous
#include <cuda_runtime.h>
#include <math.h>

// Problem constants
#define BB   4
#define CIN  32
#define CH   64
#define HH   24
#define WW   24
#define HWN  576          // 24*24
#define TT   5
#define DK   32
#define DV   32
#define NHN  4
#define GG   4
#define HEADS 64          // B*G*NH
#define TKEYS 2880        // T*HW
#define KC    6           // key chunks
#define KPC   480         // keys per chunk
#define ATTN_THREADS 192  // 3 queries per thread, 6 full warps

// ---------------- scratch (device globals; no allocation allowed) -------------
__device__ float  g_xg[BB*GG*CH*HWN];        // conv on inputs, 4 gates x 64 ch
__device__ float  g_co[BB*GG*(CH-DV)*HWN];   // conv on rep, 4 gates x 32 ch
__device__ float4 g_q[HEADS*HWN*2];          // Q [head][q][8] (scaled)
__device__ float4 g_K[HEADS*TKEYS*2];        // K [head][j][8]
__device__ float4 g_V[HEADS*TKEYS*2];        // V [head][j][8]
__device__ float  g_L[KC*HEADS*HWN];         // partial exp-sums
__device__ float4 g_A[KC*HEADS*HWN*2];       // partial weighted V sums
__device__ float  g_attnp[BB*GG*DV*HWN];     // projected attention

// ---------------- conv: 4 gates per thread, 2 pixels per thread --------------
template<int IC, int OC, int WHICH>
__global__ __launch_bounds__(288)
void conv4g_kernel(const float* __restrict__ in,   // [B][IC][24][24]
                   const float* __restrict__ w,    // [G][OC][IC][3][3]
                   const float* __restrict__ bias) // [G][OC]
{
    const int oc = blockIdx.x;
    const int b  = blockIdx.y;
    const int tid = threadIdx.x;

    __shared__ float ws[GG*IC*9];
    for (int i = tid; i < GG*IC*9; i += 288) {
        int g = i / (IC*9);
        int r = i - g*(IC*9);
        ws[i] = w[(g*OC + oc)*IC*9 + r];
    }
    __syncthreads();

    const int p0 = tid, p1 = tid + 288;
    const int y0 = p0 / WW, x0 = p0 % WW;
    const int y1 = p1 / WW, x1 = p1 % WW;

    float acc0[GG], acc1[GG];
    #pragma unroll
    for (int g = 0; g < GG; g++) {
        float bv = __ldg(bias + g*OC + oc);
        acc0[g] = bv; acc1[g] = bv;
    }

    for (int ic = 0; ic < IC; ic++) {
        const float* ip = in + (b*IC + ic)*HWN;
        float v0[9], v1[9];
        #pragma unroll
        for (int ky = 0; ky < 3; ky++) {
            #pragma unroll
            for (int kx = 0; kx < 3; kx++) {
                int iy = y0 + ky - 1, ix = x0 + kx - 1;
                v0[ky*3+kx] = (iy >= 0 && iy < HH && ix >= 0 && ix < WW)
                              ? __ldg(ip + iy*WW + ix) : 0.f;
                int jy = y1 + ky - 1, jx = x1 + kx - 1;
                v1[ky*3+kx] = (jy >= 0 && jy < HH && jx >= 0 && jx < WW)
                              ? __ldg(ip + jy*WW + jx) : 0.f;
            }
        }
        #pragma unroll
        for (int g = 0; g < GG; g++) {
            const float* wp = &ws[(g*IC + ic)*9];
            #pragma unroll
            for (int kk = 0; kk < 9; kk++) {
                float wv = wp[kk];
                acc0[g] = fmaf(v0[kk], wv, acc0[g]);
                acc1[g] = fmaf(v1[kk], wv, acc1[g]);
            }
        }
    }
    float* out = (WHICH == 0) ? g_xg : g_co;
    #pragma unroll
    for (int g = 0; g < GG; g++) {
        out[((b*GG + g)*OC + oc)*HWN + p0] = acc0[g];
        out[((b*GG + g)*OC + oc)*HWN + p1] = acc1[g];
    }
}

// ---------------- KV projection, register-tiled ------------------------------
// One block per (t, b, g, half). 576 threads: og = tid&3 (8 outputs each),
// pg = tid>>2 (4 pixels each). Weights transposed in smem: wt[c][e].
// Per c-step: 1 LDG.128 (4 pixels) + 2 LDS.128 (8 weights) -> 32 FMA.
template<int HALF>
__global__ __launch_bounds__(576)
void kv_tiled_kernel(const float* __restrict__ hist, // [B][T][CH][HW]
                     const float* __restrict__ kvw,  // [G][DK+DV][CH]
                     const float* __restrict__ kvb)  // [G][DK+DV]
{
    const int t  = blockIdx.x;
    const int b  = blockIdx.y >> 2;
    const int g  = blockIdx.y & 3;
    const int tid = threadIdx.x;
    const int og = tid & 3;        // output group: outputs og*8 .. og*8+7
    const int pg = tid >> 2;       // pixel group: pixels pg*4 .. pg*4+3

    __shared__ float wt[CH*32];    // [c][e] transposed
    __shared__ float bs[32];
    for (int i = tid; i < CH*32; i += 576) {
        int e = i & 31, c = i >> 5;
        wt[c*32 + e] = kvw[(g*(DK+DV) + HALF*32 + e)*CH + c];
    }
    if (tid < 32) bs[tid] = kvb[g*(DK+DV) + HALF*32 + tid];
    __syncthreads();

    float acc[8][4];
    #pragma unroll
    for (int o = 0; o < 8; o++)
        #pragma unroll
        for (int p = 0; p < 4; p++) acc[o][p] = 0.f;

    const float* hb = hist + ((b*TT + t)*CH)*HWN + pg*4;
    #pragma unroll 4
    for (int c = 0; c < CH; c++) {
        float4 px = *(const float4*)(hb + c*HWN);
        float4 w0 = *(const float4*)(&wt[c*32 + og*8]);
        float4 w1 = *(const float4*)(&wt[c*32 + og*8 + 4]);
        float wv[8] = {w0.x, w0.y, w0.z, w0.w, w1.x, w1.y, w1.z, w1.w};
        float pv[4] = {px.x, px.y, px.z, px.w};
        #pragma unroll
        for (int o = 0; o < 8; o++)
            #pragma unroll
            for (int p = 0; p < 4; p++)
                acc[o][p] = fmaf(wv[o], pv[p], acc[o][p]);
    }

    // outputs og*8..og*8+7 span exactly head-dim slot n == og
    const int head = (b*GG + g)*NHN + og;
    float4* dst = (HALF == 0) ? g_K : g_V;
    float bb[8];
    #pragma unroll
    for (int o = 0; o < 8; o++) bb[o] = bs[og*8 + o];
    #pragma unroll
    for (int p = 0; p < 4; p++) {
        int j = t*HWN + pg*4 + p;
        dst[(head*TKEYS + j)*2    ] = make_float4(acc[0][p]+bb[0], acc[1][p]+bb[1],
                                                  acc[2][p]+bb[2], acc[3][p]+bb[3]);
        dst[(head*TKEYS + j)*2 + 1] = make_float4(acc[4][p]+bb[4], acc[5][p]+bb[5],
                                                  acc[6][p]+bb[6], acc[7][p]+bb[7]);
    }
}

// ---------------- Q projection, register-tiled (2 pixels/thread) -------------
__global__ __launch_bounds__(576)
void q_tiled_kernel(const float* __restrict__ rep,  // [B][CH][HW]
                    const float* __restrict__ qw,   // [G][DK][CH]
                    const float* __restrict__ qb)   // [G][DK]
{
    const int b  = blockIdx.x >> 2;
    const int g  = blockIdx.x & 3;
    const int ph = blockIdx.y;          // pixel half (288 each)
    const int tid = threadIdx.x;
    const int og = tid & 3;
    const int pg = tid >> 2;            // 0..143
    const int px0 = ph*288 + pg*2;

    __shared__ float wt[CH*32];
    __shared__ float bs[32];
    for (int i = tid; i < CH*32; i += 576) {
        int e = i & 31, c = i >> 5;
        wt[c*32 + e] = qw[(g*DK + e)*CH + c];
    }
    if (tid < 32) bs[tid] = qb[g*DK + tid];
    __syncthreads();

    float acc[8][2];
    #pragma unroll
    for (int o = 0; o < 8; o++) { acc[o][0] = 0.f; acc[o][1] = 0.f; }

    const float* rb = rep + (b*CH)*HWN + px0;
    #pragma unroll 4
    for (int c = 0; c < CH; c++) {
        float2 px = *(const float2*)(rb + c*HWN);
        float4 w0 = *(const float4*)(&wt[c*32 + og*8]);
        float4 w1 = *(const float4*)(&wt[c*32 + og*8 + 4]);
        float wv[8] = {w0.x, w0.y, w0.z, w0.w, w1.x, w1.y, w1.z, w1.w};
        #pragma unroll
        for (int o = 0; o < 8; o++) {
            acc[o][0] = fmaf(wv[o], px.x, acc[o][0]);
            acc[o][1] = fmaf(wv[o], px.y, acc[o][1]);
        }
    }

    const float scale = 0.35355339059327373f; // 8^-0.5
    const int head = (b*GG + g)*NHN + og;
    float bb[8];
    #pragma unroll
    for (int o = 0; o < 8; o++) bb[o] = bs[og*8 + o];
    #pragma unroll
    for (int p = 0; p < 2; p++) {
        int hw = px0 + p;
        g_q[(head*HWN + hw)*2    ] = make_float4((acc[0][p]+bb[0])*scale, (acc[1][p]+bb[1])*scale,
                                                 (acc[2][p]+bb[2])*scale, (acc[3][p]+bb[3])*scale);
        g_q[(head*HWN + hw)*2 + 1] = make_float4((acc[4][p]+bb[4])*scale, (acc[5][p]+bb[5])*scale,
                                                 (acc[6][p]+bb[6])*scale, (acc[7][p]+bb[7])*scale);
    }
}

// ---------------- attention: 3 queries/thread, exp without max ----------------
__global__ __launch_bounds__(ATTN_THREADS)
void attn_kernel()
{
    const int head = blockIdx.x;       // 0..63
    const int kc   = blockIdx.y;       // 0..5
    const int tid  = threadIdx.x;

    const int q0 = tid, q1 = tid + 192, q2 = tid + 384;

    const float4* Qp = g_q + head*HWN*2;
    float4 qA0 = __ldg(Qp + q0*2), qB0 = __ldg(Qp + q0*2 + 1);
    float4 qA1 = __ldg(Qp + q1*2), qB1 = __ldg(Qp + q1*2 + 1);
    float4 qA2 = __ldg(Qp + q2*2), qB2 = __ldg(Qp + q2*2 + 1);

    const float4* Kp = g_K + (head*TKEYS + kc*KPC)*2;
    const float4* Vp = g_V + (head*TKEYS + kc*KPC)*2;

    float l0 = 0.f, l1 = 0.f, l2 = 0.f;
    float a0[8], a1[8], a2[8];
    #pragma unroll
    for (int d = 0; d < 8; d++) { a0[d]=0.f; a1[d]=0.f; a2[d]=0.f; }

    #pragma unroll 2
    for (int j = 0; j < KPC; j++) {
        float4 ka = __ldg(Kp + j*2);
        float4 kb = __ldg(Kp + j*2 + 1);
        float s0 = qA0.x*ka.x + qA0.y*ka.y + qA0.z*ka.z + qA0.w*ka.w
                 + qB0.x*kb.x + qB0.y*kb.y + qB0.z*kb.z + qB0.w*kb.w;
        float s1 = qA1.x*ka.x + qA1.y*ka.y + qA1.z*ka.z + qA1.w*ka.w
                 + qB1.x*kb.x + qB1.y*kb.y + qB1.z*kb.z + qB1.w*kb.w;
        float s2 = qA2.x*ka.x + qA2.y*ka.y + qA2.z*ka.z + qA2.w*ka.w
                 + qB2.x*kb.x + qB2.y*kb.y + qB2.z*kb.z + qB2.w*kb.w;
        float p0 = __expf(s0);
        float p1 = __expf(s1);
        float p2 = __expf(s2);
        l0 += p0; l1 += p1; l2 += p2;
        float4 va = __ldg(Vp + j*2);
        float4 vb = __ldg(Vp + j*2 + 1);
        a0[0]=fmaf(p0,va.x,a0[0]); a0[1]=fmaf(p0,va.y,a0[1]); a0[2]=fmaf(p0,va.z,a0[2]); a0[3]=fmaf(p0,va.w,a0[3]);
        a0[4]=fmaf(p0,vb.x,a0[4]); a0[5]=fmaf(p0,vb.y,a0[5]); a0[6]=fmaf(p0,vb.z,a0[6]); a0[7]=fmaf(p0,vb.w,a0[7]);
        a1[0]=fmaf(p1,va.x,a1[0]); a1[1]=fmaf(p1,va.y,a1[1]); a1[2]=fmaf(p1,va.z,a1[2]); a1[3]=fmaf(p1,va.w,a1[3]);
        a1[4]=fmaf(p1,vb.x,a1[4]); a1[5]=fmaf(p1,vb.y,a1[5]); a1[6]=fmaf(p1,vb.z,a1[6]); a1[7]=fmaf(p1,vb.w,a1[7]);
        a2[0]=fmaf(p2,va.x,a2[0]); a2[1]=fmaf(p2,va.y,a2[1]); a2[2]=fmaf(p2,va.z,a2[2]); a2[3]=fmaf(p2,va.w,a2[3]);
        a2[4]=fmaf(p2,vb.x,a2[4]); a2[5]=fmaf(p2,vb.y,a2[5]); a2[6]=fmaf(p2,vb.z,a2[6]); a2[7]=fmaf(p2,vb.w,a2[7]);
    }

    const int base = (kc*HEADS + head)*HWN;
    g_L[base + q0] = l0;
    g_L[base + q1] = l1;
    g_L[base + q2] = l2;
    g_A[(base + q0)*2    ] = make_float4(a0[0], a0[1], a0[2], a0[3]);
    g_A[(base + q0)*2 + 1] = make_float4(a0[4], a0[5], a0[6], a0[7]);
    g_A[(base + q1)*2    ] = make_float4(a1[0], a1[1], a1[2], a1[3]);
    g_A[(base + q1)*2 + 1] = make_float4(a1[4], a1[5], a1[6], a1[7]);
    g_A[(base + q2)*2    ] = make_float4(a2[0], a2[1], a2[2], a2[3]);
    g_A[(base + q2)*2 + 1] = make_float4(a2[4], a2[5], a2[6], a2[7]);
}

// ---------------- combine partials + output projection ----------------------
__global__ __launch_bounds__(192)
void proj_kernel(const float* __restrict__ pw,  // [G][DV][DV]
                 const float* __restrict__ pb)  // [G][DV]
{
    const int b = blockIdx.x, g = blockIdx.y, hwc = blockIdx.z;
    const int tid = threadIdx.x;
    const int hw = hwc*192 + tid;

    __shared__ float ws[DV*DV];
    for (int i = tid; i < DV*DV; i += 192) ws[i] = pw[g*DV*DV + i];
    __syncthreads();

    float av[DV];
    #pragma unroll
    for (int n = 0; n < NHN; n++) {
        int head = (b*GG + g)*NHN + n;
        int qi = head*HWN + hw;
        float l = 0.f;
        float4 s0 = make_float4(0.f,0.f,0.f,0.f);
        float4 s1 = make_float4(0.f,0.f,0.f,0.f);
        #pragma unroll
        for (int kc = 0; kc < KC; kc++) {
            int idx = kc*HEADS*HWN + qi;
            l += g_L[idx];
            float4 t0 = g_A[idx*2], t1 = g_A[idx*2 + 1];
            s0.x += t0.x; s0.y += t0.y; s0.z += t0.z; s0.w += t0.w;
            s1.x += t1.x; s1.y += t1.y; s1.z += t1.z; s1.w += t1.w;
        }
        float inv = 1.f / l;
        av[n*8 + 0] = s0.x*inv; av[n*8 + 1] = s0.y*inv;
        av[n*8 + 2] = s0.z*inv; av[n*8 + 3] = s0.w*inv;
        av[n*8 + 4] = s1.x*inv; av[n*8 + 5] = s1.y*inv;
        av[n*8 + 6] = s1.z*inv; av[n*8 + 7] = s1.w*inv;
    }

    #pragma unroll 4
    for (int dout = 0; dout < DV; dout++) {
        float o = __ldg(pb + g*DV + dout);
        #pragma unroll
        for (int di = 0; di < DV; di++) o = fmaf(av[di], ws[dout*DV + di], o);
        g_attnp[((b*GG + g)*DV + dout)*HWN + hw] = o;
    }
}

// ---------------- LSTM gates ------------------------------------------------
__device__ __forceinline__ float sigmf(float x) { return 1.f / (1.f + __expf(-x)); }

__global__ __launch_bounds__(576)
void gates_kernel(const float* __restrict__ c_in,
                  const float* __restrict__ Wci,
                  const float* __restrict__ Wcf,
                  const float* __restrict__ Wco,
                  float* __restrict__ out)
{
    const int b  = blockIdx.x >> 6;
    const int ch = blockIdx.x & 63;
    const int hw = threadIdx.x;

    float pre[GG];
    #pragma unroll
    for (int g = 0; g < GG; g++) {
        float x = g_xg[((b*GG + g)*CH + ch)*HWN + hw];
        float y = (ch < 32) ? g_co[((b*GG + g)*(CH-DV) + ch)*HWN + hw]
                            : g_attnp[((b*GG + g)*DV + (ch - 32))*HWN + hw];
        pre[g] = x + y;
    }

    float c  = __ldg(c_in + (b*CH + ch)*HWN + hw);
    float ci = __ldg(Wci + ch*HWN + hw);
    float cf = __ldg(Wcf + ch*HWN + hw);
    float co = __ldg(Wco + ch*HWN + hw);

    float i_t = sigmf(pre[0] + c*ci);
    float f_t = sigmf(pre[1] + c*cf + 1.0f);
    float c_t = f_t*c + i_t*tanhf(pre[2]);
    float o_t = sigmf(pre[3] + c_t*co);
    float h_t = o_t*tanhf(c_t);

    const int idx = (b*CH + ch)*HWN + hw;
    out[idx] = h_t;
    out[BB*CH*HWN + idx] = c_t;
}

// ---------------- launcher ---------------------------------------------------
extern "C" void kernel_launch(void* const* d_in, const int* in_sizes, int n_in,
                              void* d_out, int out_size)
{
    const float* inputs  = (const float*)d_in[0];
    const float* rep     = (const float*)d_in[1];
    const float* c_in    = (const float*)d_in[2];
    const float* history = (const float*)d_in[3];
    const float* Wx_w    = (const float*)d_in[4];
    const float* Wx_b    = (const float*)d_in[5];
    const float* conv_w  = (const float*)d_in[6];
    const float* conv_b  = (const float*)d_in[7];
    const float* q_w     = (const float*)d_in[8];
    const float* q_b     = (const float*)d_in[9];
    const float* kv_w    = (const float*)d_in[10];
    const float* kv_b    = (const float*)d_in[11];
    const float* proj_w  = (const float*)d_in[12];
    const float* proj_b  = (const float*)d_in[13];
    const float* Wci     = (const float*)d_in[14];
    const float* Wcf     = (const float*)d_in[15];
    const float* Wco     = (const float*)d_in[16];
    float* out = (float*)d_out;
    (void)in_sizes; (void)n_in; (void)out_size;

    // convs
    conv4g_kernel<CIN, CH, 0><<<dim3(CH, BB), 288>>>(inputs, Wx_w, Wx_b);
    conv4g_kernel<CH, CH-DV, 1><<<dim3(CH-DV, BB), 288>>>(rep, conv_w, conv_b);
    // projections
    q_tiled_kernel<<<dim3(BB*GG, 2), 576>>>(rep, q_w, q_b);
    kv_tiled_kernel<0><<<dim3(TT, BB*GG), 576>>>(history, kv_w, kv_b);
    kv_tiled_kernel<1><<<dim3(TT, BB*GG), 576>>>(history, kv_w, kv_b);
    // attention (partials over 6 key chunks)
    attn_kernel<<<dim3(HEADS, KC), ATTN_THREADS>>>();
    // combine + projection
    proj_kernel<<<dim3(BB, GG, 3), 192>>>(proj_w, proj_b);
    // LSTM gates -> h_t, c_t
    gates_kernel<<<BB*CH, HWN>>>(c_in, Wci, Wcf, Wco, out);
}